// round 5
// baseline (speedup 1.0000x reference)
#include <cuda_runtime.h>
#include <cstdint>

#define BB   256
#define LL   512
#define DD   64
#define NID  10000
#define TMAX 16      // smem table rows; counts beyond take the (never-hit) direct path

// Direct computation of g(a)[e..e+3] for the never-in-practice case a >= nrows.
__device__ __noinline__ float4 g_direct(uint32_t a, int lane,
                                        const float* __restrict__ w1s,
                                        const float* __restrict__ b1s,
                                        const float* __restrict__ b2,
                                        const float* __restrict__ W2) {
    float4 s = ((const float4*)b2)[lane];
    const int e = lane * 4;
    for (int d = 0; d < DD; ++d) {
        float hv = fmaf((float)a, w1s[d], b1s[d]);
        hv = hv > 0.f ? hv : 0.f;
        s.x = fmaf(hv, __ldg(&W2[(e + 0) * DD + d]), s.x);
        s.y = fmaf(hv, __ldg(&W2[(e + 1) * DD + d]), s.y);
        s.z = fmaf(hv, __ldg(&W2[(e + 2) * DD + d]), s.z);
        s.w = fmaf(hv, __ldg(&W2[(e + 3) * DD + d]), s.w);
    }
    return s;
}

// ---------------------------------------------------------------------------
// One CTA per (batch, role). role 0 -> src_feat rows, role 1 -> dst_feat rows.
// Each CTA builds the full packed histogram of its batch (lo16 = count in src
// seq, hi16 = count in dst seq), a tiny smem g-table, then streams 128 KB out.
// 46.7 KB static smem -> 4 CTAs/SM -> 2048 thr/SM, grid 512 = single wave.
// ---------------------------------------------------------------------------
__global__ void __launch_bounds__(512, 4) fused_encode(
        const int* __restrict__ src,
        const int* __restrict__ dst,
        const float* __restrict__ W1,
        const float* __restrict__ b1,
        const float* __restrict__ W2,
        const float* __restrict__ b2,
        float* __restrict__ out) {
    __shared__ __align__(16) uint32_t hist[NID];      // 40000 B
    __shared__ __align__(16) float    table[TMAX*DD]; //  4096 B
    __shared__ __align__(16) uint32_t cnt[LL];        //  2048 B
    __shared__ float w1s[DD], b1s[DD];                //   512 B
    __shared__ uint32_t maxc;

    const int t    = threadIdx.x;
    const int b    = blockIdx.x >> 1;
    const int role = blockIdx.x & 1;

    // phase 0: zero histogram (128-bit), cache W1/b1, load ids
    const uint4 z = make_uint4(0u, 0u, 0u, 0u);
    #pragma unroll
    for (int i = t; i < NID / 4; i += 512) ((uint4*)hist)[i] = z;
    if (t < DD) { w1s[t] = W1[t]; b1s[t] = b1[t]; }
    if (t == 0) maxc = 0u;

    const int sid = src[b * LL + t];
    const int did = dst[b * LL + t];
    const int oid = role ? did : sid;      // this CTA's own-role id at position t
    __syncthreads();

    // phase 1: packed dual histogram
    atomicAdd(&hist[sid], 1u);
    atomicAdd(&hist[did], 0x10000u);
    __syncthreads();

    // phase 2: per-position packed counts for own role; batch-wide max count
    const uint32_t c = oid ? hist[oid] : 0u;   // padding id 0 -> (0,0)
    cnt[t] = c;
    uint32_t m = max(c & 0xFFFFu, c >> 16);
    m = __reduce_max_sync(0xFFFFFFFFu, m);
    if ((t & 31) == 0) atomicMax(&maxc, m);
    __syncthreads();

    const int nrows = min((int)maxc + 1, TMAX);

    // phase 3: build g-table rows 0..nrows-1 (h recomputed per entry; tiny)
    for (int idx = t; idx < nrows * DD; idx += 512) {
        const int a = idx >> 6, e = idx & 63;
        const float fa = (float)a;
        float s = __ldg(&b2[e]);
        const float* w2r = W2 + e * DD;
        #pragma unroll 8
        for (int d = 0; d < DD; ++d) {
            float hv = fmaf(fa, w1s[d], b1s[d]);
            hv = hv > 0.f ? hv : 0.f;
            s = fmaf(hv, __ldg(&w2r[d]), s);
        }
        table[idx] = s;
    }
    __syncthreads();

    // phase 4: stream 512 rows x 256 B, float4-coalesced (16 lanes per row)
    const int lane = t & 15;
    const float4* T4 = (const float4*)table;
    float4* __restrict__ o =
        (float4*)(out + ((size_t)role * BB * LL + (size_t)b * LL) * DD);

    for (int r = (t >> 4); r < LL; r += 32) {
        const uint32_t cc = cnt[r];
        const uint32_t a0 = cc & 0xFFFFu, a1 = cc >> 16;
        float4 v0 = (a0 < (uint32_t)nrows) ? T4[a0 * 16 + lane]
                                           : g_direct(a0, lane, w1s, b1s, b2, W2);
        float4 v1 = (a1 < (uint32_t)nrows) ? T4[a1 * 16 + lane]
                                           : g_direct(a1, lane, w1s, b1s, b2, W2);
        float4 w;
        w.x = v0.x + v1.x; w.y = v0.y + v1.y;
        w.z = v0.z + v1.z; w.w = v0.w + v1.w;
        o[r * 16 + lane] = w;
    }
}

// ---------------------------------------------------------------------------
// Inputs: 0 src_ids, 1 dst_ids, 2 W1(D,1), 3 b1(D), 4 W2(D,D), 5 b2(D)
// Output: [src_feat | dst_feat], each B*L*D f32.
// ---------------------------------------------------------------------------
extern "C" void kernel_launch(void* const* d_in, const int* in_sizes, int n_in,
                              void* d_out, int out_size) {
    const int*   src = (const int*)d_in[0];
    const int*   dst = (const int*)d_in[1];
    const float* W1  = (const float*)d_in[2];
    const float* b1  = (const float*)d_in[3];
    const float* W2  = (const float*)d_in[4];
    const float* b2  = (const float*)d_in[5];
    float* out = (float*)d_out;

    fused_encode<<<2 * BB, 512>>>(src, dst, W1, b1, W2, b2, out);
}

// round 6
// speedup vs baseline: 1.9196x; 1.9196x over previous
#include <cuda_runtime.h>
#include <cstdint>

#define BB   256
#define LL   512
#define DD   64
#define NID  10000
#define TMAX 16      // smem table rows; larger counts take the uniform cold path

// ---------------------------------------------------------------------------
// One CTA per (batch, role). role 0 -> src_feat rows, role 1 -> dst_feat rows.
// Packed histogram (lo16 = count in src seq, hi16 = count in dst seq), tiny
// smem g-table, stream 128 KB out. 46.9 KB static smem -> 4 CTAs/SM, grid 512
// -> single wave. No calls / per-element branches in the hot loop.
// ---------------------------------------------------------------------------
__global__ void __launch_bounds__(512, 4) fused_encode(
        const int* __restrict__ src,
        const int* __restrict__ dst,
        const float* __restrict__ W1,
        const float* __restrict__ b1,
        const float* __restrict__ W2,
        const float* __restrict__ b2,
        float* __restrict__ out) {
    __shared__ __align__(16) uint32_t hist[NID];        // 40000 B
    __shared__ __align__(16) float    table[TMAX * DD]; //  4096 B
    __shared__ __align__(16) uint32_t cnt[LL];          //  2048 B
    __shared__ float w1s[DD], b1s[DD], b2s[DD];         //   768 B
    __shared__ uint32_t maxc;

    const int t    = threadIdx.x;
    const int b    = blockIdx.x >> 1;
    const int role = blockIdx.x & 1;

    // phase 0: zero histogram (128-bit), cache small params, load ids
    const uint4 z = make_uint4(0u, 0u, 0u, 0u);
    #pragma unroll
    for (int i = t; i < NID / 4; i += 512) ((uint4*)hist)[i] = z;
    if (t < DD)                 w1s[t]       = W1[t];
    else if (t < 2 * DD)        b1s[t - DD]  = b1[t - DD];
    else if (t < 3 * DD)        b2s[t - 2*DD] = b2[t - 2*DD];
    if (t == 0) maxc = 0u;

    const int sid = src[b * LL + t];
    const int did = dst[b * LL + t];
    const int oid = role ? did : sid;          // this CTA's own-role id at pos t
    __syncthreads();

    // phase 1: packed dual histogram
    atomicAdd(&hist[sid], 1u);
    atomicAdd(&hist[did], 0x10000u);
    __syncthreads();

    // phase 2: per-position packed counts for own role; batch-wide max
    const uint32_t c = oid ? hist[oid] : 0u;   // padding id 0 -> (0,0)
    cnt[t] = c;
    uint32_t m = max(c & 0xFFFFu, c >> 16);
    m = __reduce_max_sync(0xFFFFFFFFu, m);
    if ((t & 31) == 0) atomicMax(&maxc, m);
    __syncthreads();

    const int nrows = (int)maxc + 1;
    const int lane  = t & 15;
    float4* __restrict__ o =
        (float4*)(out + ((size_t)role * BB * LL + (size_t)b * LL) * DD);

    if (nrows <= TMAX) {
        // phase 3 (hot): build g-table rows 0..nrows-1; one entry per thread.
        // W2 row read as 16 independent LDG.128 (L1-resident after 1st wave).
        if (t < nrows * DD) {
            const int a = t >> 6, e = t & 63;
            const float fa = (float)a;
            float s = b2s[e];
            const float4* w2r4 = (const float4*)(W2 + e * DD);
            #pragma unroll 4
            for (int j = 0; j < 16; ++j) {
                const float4 w4 = __ldg(&w2r4[j]);
                const int d = j * 4;
                const float h0 = fmaxf(fmaf(fa, w1s[d + 0], b1s[d + 0]), 0.f);
                const float h1 = fmaxf(fmaf(fa, w1s[d + 1], b1s[d + 1]), 0.f);
                const float h2 = fmaxf(fmaf(fa, w1s[d + 2], b1s[d + 2]), 0.f);
                const float h3 = fmaxf(fmaf(fa, w1s[d + 3], b1s[d + 3]), 0.f);
                s = fmaf(h0, w4.x, s);
                s = fmaf(h1, w4.y, s);
                s = fmaf(h2, w4.z, s);
                s = fmaf(h3, w4.w, s);
            }
            table[t] = s;
        }
        __syncthreads();

        // phase 4 (hot): stream 512 rows x 256 B, float4-coalesced.
        const float4* T4 = (const float4*)table;
        #pragma unroll
        for (int r = (t >> 4); r < LL; r += 32) {
            const uint32_t cc = cnt[r];
            const float4 v0 = T4[(cc & 0xFFFFu) * 16 + lane];
            const float4 v1 = T4[(cc >> 16)     * 16 + lane];
            float4 w;
            w.x = v0.x + v1.x; w.y = v0.y + v1.y;
            w.z = v0.z + v1.z; w.w = v0.w + v1.w;
            o[r * 16 + lane] = w;
        }
    } else {
        // cold path (CTA-uniform, never taken with this data): direct compute.
        for (int r = (t >> 4); r < LL; r += 32) {
            const uint32_t cc = cnt[r];
            const float a0 = (float)(cc & 0xFFFFu);
            const float a1 = (float)(cc >> 16);
            float4 s;
            s.x = 2.f * b2s[lane * 4 + 0];
            s.y = 2.f * b2s[lane * 4 + 1];
            s.z = 2.f * b2s[lane * 4 + 2];
            s.w = 2.f * b2s[lane * 4 + 3];
            for (int d = 0; d < DD; ++d) {
                const float h = fmaxf(fmaf(a0, w1s[d], b1s[d]), 0.f)
                              + fmaxf(fmaf(a1, w1s[d], b1s[d]), 0.f);
                s.x = fmaf(h, __ldg(&W2[(lane * 4 + 0) * DD + d]), s.x);
                s.y = fmaf(h, __ldg(&W2[(lane * 4 + 1) * DD + d]), s.y);
                s.z = fmaf(h, __ldg(&W2[(lane * 4 + 2) * DD + d]), s.z);
                s.w = fmaf(h, __ldg(&W2[(lane * 4 + 3) * DD + d]), s.w);
            }
            o[r * 16 + lane] = s;
        }
    }
}

// ---------------------------------------------------------------------------
// Inputs: 0 src_ids, 1 dst_ids, 2 W1(D,1), 3 b1(D), 4 W2(D,D), 5 b2(D)
// Output: [src_feat | dst_feat], each B*L*D f32.
// ---------------------------------------------------------------------------
extern "C" void kernel_launch(void* const* d_in, const int* in_sizes, int n_in,
                              void* d_out, int out_size) {
    const int*   src = (const int*)d_in[0];
    const int*   dst = (const int*)d_in[1];
    const float* W1  = (const float*)d_in[2];
    const float* b1  = (const float*)d_in[3];
    const float* W2  = (const float*)d_in[4];
    const float* b2  = (const float*)d_in[5];
    float* out = (float*)d_out;

    fused_encode<<<2 * BB, 512>>>(src, dst, W1, b1, W2, b2, out);
}

// round 7
// speedup vs baseline: 2.0932x; 1.0904x over previous
#include <cuda_runtime.h>
#include <cstdint>

#define BB   256
#define LL   512
#define DD   64
#define NID  10000
#define TROWS 8        // fixed table rows, built unconditionally

// ---------------------------------------------------------------------------
// One CTA per batch. Packed histogram (lo16 = count in src seq, hi16 = count
// in dst seq). 8-row g-table built concurrently with the atomic phase.
// Store phase: register-cached "mode" row (count pattern (1,0)/(0,1)) makes
// the common case a bare STG.128; rare rows take the smem table fallback.
// ---------------------------------------------------------------------------
__global__ void __launch_bounds__(512) fused_encode(
        const int* __restrict__ src,
        const int* __restrict__ dst,
        const float* __restrict__ W1,
        const float* __restrict__ b1,
        const float* __restrict__ W2,
        const float* __restrict__ b2,
        float* __restrict__ out) {
    __shared__ __align__(16) uint32_t hist[NID];          // 40000 B
    __shared__ __align__(16) float    table[TROWS * DD];  //  2048 B
    __shared__ __align__(16) uint32_t cs[LL];             //  2048 B
    __shared__ __align__(16) uint32_t cd[LL];             //  2048 B
    __shared__ float w1s[DD], b1s[DD], b2s[DD];           //   768 B
    __shared__ uint32_t maxc;

    const int t = threadIdx.x;
    const int b = blockIdx.x;

    // ---- P0: zero histogram (128-bit), stage small params, load ids ----
    const uint4 z = make_uint4(0u, 0u, 0u, 0u);
    #pragma unroll
    for (int i = t; i < NID / 4; i += 512) ((uint4*)hist)[i] = z;
    if (t < DD)            w1s[t]          = W1[t];
    else if (t < 2 * DD)   b1s[t - DD]     = b1[t - DD];
    else if (t < 3 * DD)   b2s[t - 2 * DD] = b2[t - 2 * DD];
    if (t == 0) maxc = 0u;

    const int sid = src[b * LL + t];
    const int did = dst[b * LL + t];
    __syncthreads();

    // ---- P1: atomics + (concurrently) fixed 8-row table build ----
    atomicAdd(&hist[sid], 1u);
    atomicAdd(&hist[did], 0x10000u);
    {
        // one table entry per thread: 512 threads = 8 rows x 64 cols
        const int a = t >> 6, e = t & 63;
        const float fa = (float)a;
        float s = b2s[e];
        const float4* w2r4 = (const float4*)(W2 + e * DD);
        #pragma unroll 4
        for (int j = 0; j < 16; ++j) {
            const float4 w4 = __ldg(&w2r4[j]);
            const int d = j * 4;
            const float h0 = fmaxf(fmaf(fa, w1s[d + 0], b1s[d + 0]), 0.f);
            const float h1 = fmaxf(fmaf(fa, w1s[d + 1], b1s[d + 1]), 0.f);
            const float h2 = fmaxf(fmaf(fa, w1s[d + 2], b1s[d + 2]), 0.f);
            const float h3 = fmaxf(fmaf(fa, w1s[d + 3], b1s[d + 3]), 0.f);
            s = fmaf(h0, w4.x, s);
            s = fmaf(h1, w4.y, s);
            s = fmaf(h2, w4.z, s);
            s = fmaf(h3, w4.w, s);
        }
        table[t] = s;
    }
    __syncthreads();

    // ---- P2: per-position packed counts (id 0 = padding -> (0,0)); max ----
    const uint32_t hs = sid ? hist[sid] : 0u;
    const uint32_t hd = did ? hist[did] : 0u;
    cs[t] = hs;
    cd[t] = hd;
    uint32_t m = max(max(hs & 0xFFFFu, hs >> 16), max(hd & 0xFFFFu, hd >> 16));
    m = __reduce_max_sync(0xFFFFFFFFu, m);
    if ((t & 31) == 0) atomicMax(&maxc, m);
    __syncthreads();

    const int lane = t & 15;
    float4* __restrict__ osrc = (float4*)(out + (size_t)b * LL * DD);
    float4* __restrict__ odst = (float4*)(out + ((size_t)BB + b) * LL * DD);

    if (maxc < TROWS) {
        // ---- hot path ----
        const float4* T4 = (const float4*)table;
        // mode row: g(1)+g(0) == g(0)+g(1) bit-identically
        const float4 t1 = T4[16 + lane];
        const float4 t0 = T4[lane];
        float4 wmode;
        wmode.x = t1.x + t0.x; wmode.y = t1.y + t0.y;
        wmode.z = t1.z + t0.z; wmode.w = t1.w + t0.w;

        #pragma unroll 4
        for (int r = (t >> 4); r < LL; r += 32) {
            const uint32_t c = cs[r];
            float4 w;
            if (c == 1u) {
                w = wmode;
            } else {
                const float4 v0 = T4[(c & 0xFFFFu) * 16 + lane];
                const float4 v1 = T4[(c >> 16)     * 16 + lane];
                w.x = v0.x + v1.x; w.y = v0.y + v1.y;
                w.z = v0.z + v1.z; w.w = v0.w + v1.w;
            }
            osrc[r * 16 + lane] = w;
        }
        #pragma unroll 4
        for (int r = (t >> 4); r < LL; r += 32) {
            const uint32_t c = cd[r];
            float4 w;
            if (c == 0x10000u) {
                w = wmode;
            } else {
                const float4 v0 = T4[(c & 0xFFFFu) * 16 + lane];
                const float4 v1 = T4[(c >> 16)     * 16 + lane];
                w.x = v0.x + v1.x; w.y = v0.y + v1.y;
                w.z = v0.z + v1.z; w.w = v0.w + v1.w;
            }
            odst[r * 16 + lane] = w;
        }
    } else {
        // ---- cold path (CTA-uniform, never taken with this data) ----
        for (int blk = 0; blk < 2; ++blk) {
            const uint32_t* cc = blk ? cd : cs;
            float4* o = blk ? odst : osrc;
            for (int r = (t >> 4); r < LL; r += 32) {
                const uint32_t c = cc[r];
                const float a0 = (float)(c & 0xFFFFu);
                const float a1 = (float)(c >> 16);
                float4 s;
                s.x = 2.f * b2s[lane * 4 + 0];
                s.y = 2.f * b2s[lane * 4 + 1];
                s.z = 2.f * b2s[lane * 4 + 2];
                s.w = 2.f * b2s[lane * 4 + 3];
                for (int d = 0; d < DD; ++d) {
                    const float h = fmaxf(fmaf(a0, w1s[d], b1s[d]), 0.f)
                                  + fmaxf(fmaf(a1, w1s[d], b1s[d]), 0.f);
                    s.x = fmaf(h, __ldg(&W2[(lane * 4 + 0) * DD + d]), s.x);
                    s.y = fmaf(h, __ldg(&W2[(lane * 4 + 1) * DD + d]), s.y);
                    s.z = fmaf(h, __ldg(&W2[(lane * 4 + 2) * DD + d]), s.z);
                    s.w = fmaf(h, __ldg(&W2[(lane * 4 + 3) * DD + d]), s.w);
                }
                o[r * 16 + lane] = s;
            }
        }
    }
}

// ---------------------------------------------------------------------------
// Inputs: 0 src_ids, 1 dst_ids, 2 W1(D,1), 3 b1(D), 4 W2(D,D), 5 b2(D)
// Output: [src_feat | dst_feat], each B*L*D f32.
// ---------------------------------------------------------------------------
extern "C" void kernel_launch(void* const* d_in, const int* in_sizes, int n_in,
                              void* d_out, int out_size) {
    const int*   src = (const int*)d_in[0];
    const int*   dst = (const int*)d_in[1];
    const float* W1  = (const float*)d_in[2];
    const float* b1  = (const float*)d_in[3];
    const float* W2  = (const float*)d_in[4];
    const float* b2  = (const float*)d_in[5];
    float* out = (float*)d_out;

    fused_encode<<<BB, 512>>>(src, dst, W1, b1, W2, b2, out);
}